// round 3
// baseline (speedup 1.0000x reference)
#include <cuda_runtime.h>

// Problem constants
#define NN 4
#define CC 64
#define HH 96
#define WW 96
#define PP (HH * WW)       // 9216 pixels per image
#define OO 1728            // 3 * C * 9 generated kernel channels
#define KTOT 2304          // 256 * 9 reduction dim of fuse conv

// Scratch (alloc-free rule: __device__ globals)
__device__ float g_kern[(size_t)NN * OO * PP];     // per-pixel generated kernels
__device__ float g_cat[(size_t)NN * 4 * CC * PP];  // concat(x, r1, r3, r5)
__device__ float g_wT[KTOT * CC];                  // fuse_w transposed to [k][co]

// ---- packed fp32x2 helpers ----
static __device__ __forceinline__ unsigned long long pack2(float lo, float hi) {
    unsigned long long r;
    asm("mov.b64 %0, {%1,%2};" : "=l"(r) : "f"(lo), "f"(hi));
    return r;
}
static __device__ __forceinline__ void unpack2(unsigned long long v, float& lo, float& hi) {
    asm("mov.b64 {%0,%1}, %2;" : "=f"(lo), "=f"(hi) : "l"(v));
}
static __device__ __forceinline__ void fma2(unsigned long long& d, unsigned long long a, unsigned long long b) {
    asm("fma.rn.f32x2 %0, %1, %2, %3;" : "=l"(d) : "l"(a), "l"(b), "l"(d));
}

// ============================================================
// Stage 1: kern[n,o,p] = sum_k gen_w[o,k] * y[n,k,p] + gen_b[o]
// Tile 64o x 128px, 128 threads, per-thread 16co (8 f32x2 pairs) x 4px.
// ============================================================
__global__ void __launch_bounds__(128, 4) stage1_gemm(
    const float* __restrict__ gen_w, const float* __restrict__ gen_b,
    const float* __restrict__ y)
{
    __shared__ __align__(16) float As[32][68];                     // [k][o], padded
    __shared__ __align__(16) unsigned long long Bs2[32][128];      // [k][p] dup'd
    const int n  = blockIdx.z;
    const int o0 = blockIdx.y * 64;
    const int p0 = blockIdx.x * 128;
    const int tid = threadIdx.x;
    const int tx = tid & 31;       // px group: 4 px
    const int ty = tid >> 5;       // co group: 16 co

    unsigned long long acc[8][4];
#pragma unroll
    for (int i = 0; i < 8; i++)
#pragma unroll
        for (int j = 0; j < 4; j++) acc[i][j] = 0ull;

    for (int kk0 = 0; kk0 < 64; kk0 += 32) {
        __syncthreads();
#pragma unroll
        for (int t = 0; t < 4; t++) {
            int fid = tid + t * 128;          // 0..511
            int o   = fid >> 3;
            int k4  = (fid & 7) * 4;
            float4 v = *(const float4*)(gen_w + (size_t)(o0 + o) * 64 + kk0 + k4);
            As[k4 + 0][o] = v.x;
            As[k4 + 1][o] = v.y;
            As[k4 + 2][o] = v.z;
            As[k4 + 3][o] = v.w;
        }
#pragma unroll
        for (int t = 0; t < 8; t++) {
            int fid = tid + t * 128;          // 0..1023
            int k   = fid >> 5;
            int p4  = (fid & 31) * 4;
            float4 v = *(const float4*)(y + ((size_t)n * 64 + kk0 + k) * PP + p0 + p4);
            ulonglong2 d0, d1;
            d0.x = pack2(v.x, v.x); d0.y = pack2(v.y, v.y);
            d1.x = pack2(v.z, v.z); d1.y = pack2(v.w, v.w);
            *(ulonglong2*)&Bs2[k][p4]     = d0;
            *(ulonglong2*)&Bs2[k][p4 + 2] = d1;
        }
        __syncthreads();

#pragma unroll 4
        for (int k = 0; k < 32; k++) {
            ulonglong2 a01 = *(ulonglong2*)&As[k][ty * 16];
            ulonglong2 a23 = *(ulonglong2*)&As[k][ty * 16 + 4];
            ulonglong2 a45 = *(ulonglong2*)&As[k][ty * 16 + 8];
            ulonglong2 a67 = *(ulonglong2*)&As[k][ty * 16 + 12];
            ulonglong2 b01 = *(ulonglong2*)&Bs2[k][tx * 4];
            ulonglong2 b23 = *(ulonglong2*)&Bs2[k][tx * 4 + 2];
            fma2(acc[0][0], a01.x, b01.x); fma2(acc[0][1], a01.x, b01.y);
            fma2(acc[0][2], a01.x, b23.x); fma2(acc[0][3], a01.x, b23.y);
            fma2(acc[1][0], a01.y, b01.x); fma2(acc[1][1], a01.y, b01.y);
            fma2(acc[1][2], a01.y, b23.x); fma2(acc[1][3], a01.y, b23.y);
            fma2(acc[2][0], a23.x, b01.x); fma2(acc[2][1], a23.x, b01.y);
            fma2(acc[2][2], a23.x, b23.x); fma2(acc[2][3], a23.x, b23.y);
            fma2(acc[3][0], a23.y, b01.x); fma2(acc[3][1], a23.y, b01.y);
            fma2(acc[3][2], a23.y, b23.x); fma2(acc[3][3], a23.y, b23.y);
            fma2(acc[4][0], a45.x, b01.x); fma2(acc[4][1], a45.x, b01.y);
            fma2(acc[4][2], a45.x, b23.x); fma2(acc[4][3], a45.x, b23.y);
            fma2(acc[5][0], a45.y, b01.x); fma2(acc[5][1], a45.y, b01.y);
            fma2(acc[5][2], a45.y, b23.x); fma2(acc[5][3], a45.y, b23.y);
            fma2(acc[6][0], a67.x, b01.x); fma2(acc[6][1], a67.x, b01.y);
            fma2(acc[6][2], a67.x, b23.x); fma2(acc[6][3], a67.x, b23.y);
            fma2(acc[7][0], a67.y, b01.x); fma2(acc[7][1], a67.y, b01.y);
            fma2(acc[7][2], a67.y, b23.x); fma2(acc[7][3], a67.y, b23.y);
        }
    }

    const int co0 = o0 + ty * 16;
#pragma unroll
    for (int i = 0; i < 8; i++) {
        int oe = co0 + 2 * i;
        float be = gen_b[oe];
        float bo = gen_b[oe + 1];
        float e0, o0v, e1, o1v, e2, o2v, e3, o3v;
        unpack2(acc[i][0], e0, o0v);
        unpack2(acc[i][1], e1, o1v);
        unpack2(acc[i][2], e2, o2v);
        unpack2(acc[i][3], e3, o3v);
        float* de = g_kern + ((size_t)n * OO + oe) * PP + p0 + tx * 4;
        float* doo = de + PP;
        *(float4*)de  = make_float4(e0 + be, e1 + be, e2 + be, e3 + be);
        *(float4*)doo = make_float4(o0v + bo, o1v + bo, o2v + bo, o3v + bo);
    }
}

// ============================================================
// Stage 2: dynamic depthwise convs (d = 1, 3, 5) + build cat buffer
// ============================================================
__global__ void __launch_bounds__(256) stage2_dynconv(const float* __restrict__ x)
{
    const int n = blockIdx.z;
    const int c = blockIdx.y;
    const int p = blockIdx.x * 256 + threadIdx.x;
    const int h = p / WW;
    const int w = p - h * WW;

    const float* xc = x + ((size_t)n * CC + c) * PP;
    const float* kb = g_kern + ((size_t)n * OO + c * 9) * PP + p;

    float acc0 = 0.f, acc1 = 0.f, acc2 = 0.f;
#pragma unroll
    for (int tap = 0; tap < 9; tap++) {
        const int di = tap / 3 - 1;
        const int dj = tap % 3 - 1;
        {
            int hh = h + di, ww2 = w + dj;
            float xv = ((unsigned)hh < (unsigned)HH && (unsigned)ww2 < (unsigned)WW)
                           ? __ldg(xc + hh * WW + ww2) : 0.f;
            acc0 += xv * __ldg(kb + (size_t)tap * PP);
        }
        {
            int hh = h + di * 3, ww2 = w + dj * 3;
            float xv = ((unsigned)hh < (unsigned)HH && (unsigned)ww2 < (unsigned)WW)
                           ? __ldg(xc + hh * WW + ww2) : 0.f;
            acc1 += xv * __ldg(kb + (size_t)(576 + tap) * PP);
        }
        {
            int hh = h + di * 5, ww2 = w + dj * 5;
            float xv = ((unsigned)hh < (unsigned)HH && (unsigned)ww2 < (unsigned)WW)
                           ? __ldg(xc + hh * WW + ww2) : 0.f;
            acc2 += xv * __ldg(kb + (size_t)(1152 + tap) * PP);
        }
    }

    float* cb = g_cat + (size_t)n * 4 * CC * PP + p;
    cb[(size_t)c * PP]            = __ldg(xc + p);
    cb[(size_t)(CC + c) * PP]     = acc0;
    cb[(size_t)(2 * CC + c) * PP] = acc1;
    cb[(size_t)(3 * CC + c) * PP] = acc2;
}

// ============================================================
// transpose fuse_w [co][ci*9+tap] -> g_wT [k][co]
// ============================================================
__global__ void transpose_w(const float* __restrict__ fuse_w)
{
    int idx = blockIdx.x * 256 + threadIdx.x;
    if (idx < KTOT * CC) {
        int k  = idx >> 6;
        int co = idx & 63;
        g_wT[idx] = fuse_w[(size_t)co * KTOT + k];
    }
}

// ============================================================
// Stage 3: 3x3 fuse conv. CTA = half a row (48 px) x 64 co.
// grid (2, 96, 4) = 768 CTAs for occupancy. 128 threads:
// tx 8 (6 px each) x ty 16 (4 co each -> 2 f32x2 pairs).
// ci in groups of 8; 3-row x 50-px halo in smem (pre-dup'd f32x2).
// ============================================================
#define S3_G 8
__global__ void __launch_bounds__(128) stage3_conv(
    const float* __restrict__ fuse_b, float* __restrict__ out)
{
    __shared__ __align__(16) float Ws[S3_G * 9][64];                 // [kl][co]
    __shared__ __align__(16) unsigned long long Hal[S3_G][3][52];    // dup'd halo
    const int w0 = blockIdx.x * 48;
    const int h  = blockIdx.y;
    const int n  = blockIdx.z;
    const int tid = threadIdx.x;
    const int tx = tid & 7;    // px group: 6 px
    const int ty = tid >> 3;   // co group: 4 co
    const float* catn = g_cat + (size_t)n * 4 * CC * PP;

    unsigned long long acc[2][6];
#pragma unroll
    for (int i = 0; i < 2; i++)
#pragma unroll
        for (int j = 0; j < 6; j++) acc[i][j] = 0ull;

#pragma unroll 1
    for (int c0 = 0; c0 < 4 * CC; c0 += S3_G) {
        __syncthreads();
        // Ws: 72 x 64 from pre-transposed weights (1152 float4 / 128 thr = 9)
#pragma unroll
        for (int t = 0; t < 9; t++) {
            int fid = tid + t * 128;            // 0..1151
            int kl  = fid >> 4;
            int c4  = (fid & 15) * 4;
            *(float4*)&Ws[kl][c4] = *(const float4*)(g_wT + (size_t)(c0 * 9 + kl) * 64 + c4);
        }
        // Halo: 8 ci x 3 rows x 52 entries (u -> w = w0 - 1 + u), scalar coalesced
#pragma unroll
        for (int t = 0; t < 10; t++) {
            int fid = tid + t * 128;            // 0..1247
            if (fid < S3_G * 3 * 52) {
                int row  = fid / 52;            // 0..23
                int u    = fid - row * 52;      // 0..51
                int ci_l = row / 3;
                int dy   = row - ci_l * 3;
                int hh   = h + dy - 1;
                int wv   = w0 - 1 + u;
                float v = 0.f;
                if ((unsigned)hh < (unsigned)HH && (unsigned)wv < (unsigned)WW)
                    v = __ldg(catn + (size_t)(c0 + ci_l) * PP + hh * WW + wv);
                Hal[ci_l][dy][u] = pack2(v, v);
            }
        }
        __syncthreads();

#pragma unroll 1
        for (int ci_l = 0; ci_l < S3_G; ci_l++) {
#pragma unroll
            for (int dy = 0; dy < 3; dy++) {
                unsigned long long r[8];
#pragma unroll
                for (int t = 0; t < 8; t++) r[t] = Hal[ci_l][dy][tx * 6 + t];
#pragma unroll
                for (int dx = 0; dx < 3; dx++) {
                    int kl = ci_l * 9 + dy * 3 + dx;
                    ulonglong2 aA = *(ulonglong2*)&Ws[kl][ty * 4];
#pragma unroll
                    for (int j = 0; j < 6; j++) {
                        unsigned long long b = r[dx + j];
                        fma2(acc[0][j], aA.x, b);
                        fma2(acc[1][j], aA.y, b);
                    }
                }
            }
        }
    }

    // Epilogue: acc[i] = co pair (ty*4+2i, ty*4+2i+1), px = w0 + tx*6 + j
    const int px = h * WW + w0 + tx * 6;
#pragma unroll
    for (int i = 0; i < 2; i++) {
        int ce = ty * 4 + 2 * i;
        float be = __ldg(fuse_b + ce);
        float bo = __ldg(fuse_b + ce + 1);
        float e[6], o[6];
#pragma unroll
        for (int j = 0; j < 6; j++) unpack2(acc[i][j], e[j], o[j]);
        float* de = out + ((size_t)n * CC + ce) * PP + px;
        float* doo = de + PP;
#pragma unroll
        for (int j = 0; j < 3; j++) {
            *(float2*)(de + 2 * j)  = make_float2(e[2 * j] + be, e[2 * j + 1] + be);
            *(float2*)(doo + 2 * j) = make_float2(o[2 * j] + bo, o[2 * j + 1] + bo);
        }
    }
}

// ============================================================
extern "C" void kernel_launch(void* const* d_in, const int* in_sizes, int n_in,
                              void* d_out, int out_size)
{
    (void)in_sizes; (void)n_in; (void)out_size;
    const float* x      = (const float*)d_in[0];
    const float* y      = (const float*)d_in[1];
    const float* gen_w  = (const float*)d_in[2];
    const float* gen_b  = (const float*)d_in[3];
    const float* fuse_w = (const float*)d_in[4];
    const float* fuse_b = (const float*)d_in[5];
    float* out = (float*)d_out;

    transpose_w<<<(KTOT * CC + 255) / 256, 256>>>(fuse_w);

    stage1_gemm<<<dim3(PP / 128, OO / 64, NN), 128>>>(gen_w, gen_b, y);

    stage2_dynconv<<<dim3(PP / 256, CC, NN), 256>>>(x);

    stage3_conv<<<dim3(2, HH, NN), 128>>>(fuse_b, out);
}